// round 8
// baseline (speedup 1.0000x reference)
#include <cuda_runtime.h>
#include <cuda_bf16.h>
#include <cstdint>

#define NLEV 4
#define MAXS 792
#define TILE 256

// Packed table: level sizes 36/72/216/792 -> offsets 0/36/108/324, 1116 float2 (8.9KB)
#define T_OFF0 0
#define T_OFF1 36
#define T_OFF2 108
#define T_OFF3 324
#define T_TOT  1116

#define STAGE_BYTES 27648u

struct alignas(16) Stage {
    float2 nll[8][TILE];   // 16 KB (8 rows x 2048 B, each row contiguous in gmem)
    int    nidx[8][TILE];  //  8 KB (8 rows x 1024 B)
    float2 pll[TILE];      //  2 KB
    int    pidx[TILE];     //  1 KB
};                          // 27648 B

struct alignas(16) Smem {
    Stage    stage[2];      // 55296 B
    float2   tab[T_TOT];    //  8928 B
    uint64_t bar[2];        //    16 B
};

__device__ __forceinline__ uint32_t smem_u32(const void* p) {
    return (uint32_t)__cvta_generic_to_shared(p);
}
__device__ __forceinline__ void bulk_cp(void* dst, const void* src, uint32_t bytes, uint32_t mbar) {
    asm volatile(
        "cp.async.bulk.shared::cluster.global.mbarrier::complete_tx::bytes [%0], [%1], %2, [%3];"
        :: "r"(smem_u32(dst)), "l"(src), "r"(bytes), "r"(mbar) : "memory");
}
__device__ __forceinline__ void mbar_init(uint32_t mbar, uint32_t count) {
    asm volatile("mbarrier.init.shared.b64 [%0], %1;" :: "r"(mbar), "r"(count) : "memory");
}
__device__ __forceinline__ void mbar_expect_tx(uint32_t mbar, uint32_t bytes) {
    asm volatile("mbarrier.arrive.expect_tx.shared.b64 _, [%0], %1;" :: "r"(mbar), "r"(bytes) : "memory");
}
__device__ __forceinline__ void mbar_wait(uint32_t mbar, uint32_t parity) {
    asm volatile(
        "{\n\t"
        ".reg .pred P;\n\t"
        "WAIT_%=:\n\t"
        "mbarrier.try_wait.parity.acquire.cta.shared::cta.b64 P, [%0], %1, 0x989680;\n\t"
        "@P bra.uni DONE_%=;\n\t"
        "bra.uni WAIT_%=;\n\t"
        "DONE_%=:\n\t"
        "}"
        :: "r"(mbar), "r"(parity) : "memory");
}

// Issue the 18 bulk copies for one level tile into a stage (single thread).
__device__ __forceinline__ void issue_level(
    Stage* st, int l, int b0, uint32_t mbar,
    const float2* __restrict__ neigh_ll, const int* __restrict__ neigh_idx,
    const float2* __restrict__ pixel_ll, const int* __restrict__ pixel_idx, int B)
{
    mbar_expect_tx(mbar, STAGE_BYTES);
#pragma unroll
    for (int row = 0; row < 8; row++)
        bulk_cp(&st->nll[row][0],  neigh_ll  + (size_t)(l * 8 + row) * B + b0, 2048u, mbar);
#pragma unroll
    for (int row = 0; row < 8; row++)
        bulk_cp(&st->nidx[row][0], neigh_idx + (size_t)(l * 8 + row) * B + b0, 1024u, mbar);
    bulk_cp(&st->pll[0],  pixel_ll  + (size_t)l * B + b0, 2048u, mbar);
    bulk_cp(&st->pidx[0], pixel_idx + (size_t)l * B + b0, 1024u, mbar);
}

__global__ __launch_bounds__(TILE) void heal_encoding_bulk(
    const float2* __restrict__ params2,      // [NLEV, MAXS] float2
    const float2* __restrict__ pixel_ll,     // [NLEV, B]
    const float2* __restrict__ neigh_ll,     // [NLEV, 8, B]
    const int*    __restrict__ pixel_idx,    // [NLEV, B]
    const int*    __restrict__ neigh_idx,    // [NLEV, 8, B]
    float*        __restrict__ out,          // [B, 8]  out[b, 4f+l]
    int B)
{
    extern __shared__ char smem_raw[];
    Smem& s = *reinterpret_cast<Smem*>(smem_raw);
    const int tid = threadIdx.x;
    const int b0  = blockIdx.x * TILE;
    const bool full = (b0 + TILE <= B);
    const int toff[NLEV] = {T_OFF0, T_OFF1, T_OFF2, T_OFF3};

    if (full) {
        if (tid == 0) {
            mbar_init(smem_u32(&s.bar[0]), 1);
            mbar_init(smem_u32(&s.bar[1]), 1);
        }
        __syncthreads();   // barrier init visible before any complete_tx can land
        if (tid == 0) {
            issue_level(&s.stage[0], 0, b0, smem_u32(&s.bar[0]),
                        neigh_ll, neigh_idx, pixel_ll, pixel_idx, B);
            issue_level(&s.stage[1], 1, b0, smem_u32(&s.bar[1]),
                        neigh_ll, neigh_idx, pixel_ll, pixel_idx, B);
        }
    }

    // packed param table (level sizes 36/72/216/792)
    {
        const int tsz[NLEV] = {36, 72, 216, 792};
#pragma unroll
        for (int l = 0; l < NLEV; l++)
            for (int i = tid; i < tsz[l]; i += TILE)
                s.tab[toff[l] + i] = params2[l * MAXS + i];
    }
    __syncthreads();

    if (full) {
        float acc0[NLEV], acc1[NLEV];
#pragma unroll
        for (int l = 0; l < NLEV; l++) {
            const int st_i = l & 1;
            const uint32_t parity = (l >> 1) & 1;
            mbar_wait(smem_u32(&s.bar[st_i]), parity);

            Stage* st = &s.stage[st_i];
            const float2 pl = st->pll[tid];
            const int    p  = st->pidx[tid];
            const float2 r  = s.tab[toff[l] + p];
            float s0 = r.x, s1 = r.y;
#pragma unroll
            for (int j = 0; j < 8; j++) {
                const int    n  = st->nidx[j][tid];
                const float2 ll = st->nll[j][tid];
                const float dphi = ll.y - pl.y;
                const float dth  = ll.x - pl.x;
                float w = rsqrtf(fmaf(dphi, dphi, dth * dth));
                w = (n >= 0) ? w : 0.0f;
                const float2 v = s.tab[toff[l] + (n >= 0 ? n : 0)];
                s0 = fmaf(w, v.x, s0);
                s1 = fmaf(w, v.y, s1);
            }
            acc0[l] = s0; acc1[l] = s1;

            if (l + 2 < NLEV) {
                __syncthreads();   // all threads done reading stage st_i
                if (tid == 0)
                    issue_level(st, l + 2, b0, smem_u32(&s.bar[st_i]),
                                neigh_ll, neigh_idx, pixel_ll, pixel_idx, B);
            }
        }

        const int b = b0 + tid;
        float4* op = reinterpret_cast<float4*>(out + (size_t)b * 8);
        op[0] = make_float4(acc0[0], acc0[1], acc0[2], acc0[3]);
        op[1] = make_float4(acc1[0], acc1[1], acc1[2], acc1[3]);
    } else {
        // tail block: direct-LDG path, table already in smem
        const int b = b0 + tid;
        if (b < B) {
            float acc0[NLEV], acc1[NLEV];
#pragma unroll
            for (int l = 0; l < NLEV; l++) {
                int    nidx[8];
                float2 nll[8];
#pragma unroll
                for (int j = 0; j < 8; j++)
                    nidx[j] = __ldcs(neigh_idx + (size_t)(l * 8 + j) * B + b);
#pragma unroll
                for (int j = 0; j < 8; j++)
                    nll[j] = __ldcs(neigh_ll + (size_t)(l * 8 + j) * B + b);
                const int    p  = __ldcs(pixel_idx + (size_t)l * B + b);
                const float2 pl = __ldcs(pixel_ll + (size_t)l * B + b);
                const float2 r  = s.tab[toff[l] + p];
                float s0 = r.x, s1 = r.y;
#pragma unroll
                for (int j = 0; j < 8; j++) {
                    const float dphi = nll[j].y - pl.y;
                    const float dth  = nll[j].x - pl.x;
                    float w = rsqrtf(fmaf(dphi, dphi, dth * dth));
                    w = (nidx[j] >= 0) ? w : 0.0f;
                    const float2 v = s.tab[toff[l] + (nidx[j] >= 0 ? nidx[j] : 0)];
                    s0 = fmaf(w, v.x, s0);
                    s1 = fmaf(w, v.y, s1);
                }
                acc0[l] = s0; acc1[l] = s1;
            }
            float4* op = reinterpret_cast<float4*>(out + (size_t)b * 8);
            op[0] = make_float4(acc0[0], acc0[1], acc0[2], acc0[3]);
            op[1] = make_float4(acc1[0], acc1[1], acc1[2], acc1[3]);
        }
    }
}

extern "C" void kernel_launch(void* const* d_in, const int* in_sizes, int n_in,
                              void* d_out, int out_size)
{
    // metadata order: params, pixel_latlon, neigh_latlon, pixel_index, neigh_index
    const float2* params2   = (const float2*)d_in[0];
    const float2* pixel_ll  = (const float2*)d_in[1];
    const float2* neigh_ll  = (const float2*)d_in[2];
    const int*    pixel_idx = (const int*)d_in[3];
    const int*    neigh_idx = (const int*)d_in[4];
    float*        out       = (float*)d_out;

    const int B = in_sizes[3] / NLEV;   // pixel_index has NLEV*B elements

    cudaFuncSetAttribute(heal_encoding_bulk,
                         cudaFuncAttributeMaxDynamicSharedMemorySize, sizeof(Smem));

    const int grid = (B + TILE - 1) / TILE;
    heal_encoding_bulk<<<grid, TILE, sizeof(Smem)>>>(
        params2, pixel_ll, neigh_ll, pixel_idx, neigh_idx, out, B);
}

// round 9
// speedup vs baseline: 1.0118x; 1.0118x over previous
#include <cuda_runtime.h>
#include <cuda_bf16.h>
#include <cstdint>

#define NLEV 4
#define MAXS 792
#define TILE 256
#define NBLOCKS 444   // 148 SMs x 3 blocks/SM (64KB smem each)

// Packed table: level sizes 36/72/216/792 -> offsets 0/36/108/324, 1116 float2 (8.9KB)
#define T_OFF0 0
#define T_OFF1 36
#define T_OFF2 108
#define T_OFF3 324
#define T_TOT  1116

#define STAGE_BYTES 27648u

struct alignas(16) Stage {
    float2 nll[8][TILE];   // 16 KB (rows contiguous in gmem)
    int    nidx[8][TILE];  //  8 KB
    float2 pll[TILE];      //  2 KB
    int    pidx[TILE];     //  1 KB
};                          // 27648 B

struct alignas(16) Smem {
    Stage    stage[2];      // 55296 B
    float2   tab[T_TOT];    //  8928 B
    uint64_t bar[2];
};

__device__ __forceinline__ uint32_t smem_u32(const void* p) {
    return (uint32_t)__cvta_generic_to_shared(p);
}
__device__ __forceinline__ void bulk_cp(void* dst, const void* src, uint32_t bytes, uint32_t mbar) {
    asm volatile(
        "cp.async.bulk.shared::cluster.global.mbarrier::complete_tx::bytes [%0], [%1], %2, [%3];"
        :: "r"(smem_u32(dst)), "l"(src), "r"(bytes), "r"(mbar) : "memory");
}
__device__ __forceinline__ void mbar_init(uint32_t mbar, uint32_t count) {
    asm volatile("mbarrier.init.shared.b64 [%0], %1;" :: "r"(mbar), "r"(count) : "memory");
}
__device__ __forceinline__ void mbar_expect_tx(uint32_t mbar, uint32_t bytes) {
    asm volatile("mbarrier.arrive.expect_tx.shared.b64 _, [%0], %1;" :: "r"(mbar), "r"(bytes) : "memory");
}
__device__ __forceinline__ void mbar_wait(uint32_t mbar, uint32_t parity) {
    asm volatile(
        "{\n\t"
        ".reg .pred P;\n\t"
        "WAIT_%=:\n\t"
        "mbarrier.try_wait.parity.acquire.cta.shared::cta.b64 P, [%0], %1, 0x989680;\n\t"
        "@P bra.uni DONE_%=;\n\t"
        "bra.uni WAIT_%=;\n\t"
        "DONE_%=:\n\t"
        "}"
        :: "r"(mbar), "r"(parity) : "memory");
}

// Issue the 18 bulk copies for (tile, level) into a stage (single thread).
__device__ __forceinline__ void issue_item(
    Stage* st, int l, int b0, uint32_t mbar,
    const float2* __restrict__ neigh_ll, const int* __restrict__ neigh_idx,
    const float2* __restrict__ pixel_ll, const int* __restrict__ pixel_idx, int B)
{
    mbar_expect_tx(mbar, STAGE_BYTES);
#pragma unroll
    for (int row = 0; row < 8; row++)
        bulk_cp(&st->nll[row][0],  neigh_ll  + (size_t)(l * 8 + row) * B + b0, 2048u, mbar);
#pragma unroll
    for (int row = 0; row < 8; row++)
        bulk_cp(&st->nidx[row][0], neigh_idx + (size_t)(l * 8 + row) * B + b0, 1024u, mbar);
    bulk_cp(&st->pll[0],  pixel_ll  + (size_t)l * B + b0, 2048u, mbar);
    bulk_cp(&st->pidx[0], pixel_idx + (size_t)l * B + b0, 1024u, mbar);
}

__global__ __launch_bounds__(TILE) void heal_encoding_persist(
    const float2* __restrict__ params2,      // [NLEV, MAXS] float2
    const float2* __restrict__ pixel_ll,     // [NLEV, B]
    const float2* __restrict__ neigh_ll,     // [NLEV, 8, B]
    const int*    __restrict__ pixel_idx,    // [NLEV, B]
    const int*    __restrict__ neigh_idx,    // [NLEV, 8, B]
    float*        __restrict__ out,          // [B, 8]  out[b, 4f+l]
    int B)
{
    extern __shared__ char smem_raw[];
    Smem& s = *reinterpret_cast<Smem*>(smem_raw);
    const int tid = threadIdx.x;
    const int toff[NLEV] = {T_OFF0, T_OFF1, T_OFF2, T_OFF3};

    const int  ntiles   = B / TILE;                 // full tiles only
    const bool aligned  = (B & 3) == 0;             // bulk-cp 16B alignment
    // tiles for this block: blockIdx.x, +gridDim.x, ... ; items = 4 per tile
    int mytiles = 0;
    if (aligned) mytiles = (ntiles - blockIdx.x + gridDim.x - 1) / gridDim.x;
    if (mytiles < 0) mytiles = 0;
    const int nitems = mytiles * 4;

    if (tid == 0) {
        mbar_init(smem_u32(&s.bar[0]), 1);
        mbar_init(smem_u32(&s.bar[1]), 1);
    }
    __syncthreads();

    if (tid == 0 && nitems > 0) {
        // prologue: items 0 and 1 (tile = blockIdx.x, levels 0/1; nitems>=4)
        const int b0 = blockIdx.x * TILE;
        issue_item(&s.stage[0], 0, b0, smem_u32(&s.bar[0]),
                   neigh_ll, neigh_idx, pixel_ll, pixel_idx, B);
        issue_item(&s.stage[1], 1, b0, smem_u32(&s.bar[1]),
                   neigh_ll, neigh_idx, pixel_ll, pixel_idx, B);
    }

    // packed param table (level sizes 36/72/216/792), once per block
    {
        const int tsz[NLEV] = {36, 72, 216, 792};
#pragma unroll
        for (int l = 0; l < NLEV; l++)
            for (int i = tid; i < tsz[l]; i += TILE)
                s.tab[toff[l] + i] = params2[l * MAXS + i];
    }
    __syncthreads();

    float acc0[NLEV], acc1[NLEV];
    for (int i = 0; i < nitems; i++) {
        const int lvl    = i & 3;
        const int tile_k = i >> 2;
        const int tile   = blockIdx.x + tile_k * gridDim.x;
        const int b0     = tile * TILE;
        const int st_i   = i & 1;
        const uint32_t parity = (i >> 1) & 1;

        mbar_wait(smem_u32(&s.bar[st_i]), parity);

        Stage* st = &s.stage[st_i];
        const float2 pl = st->pll[tid];
        const int    p  = st->pidx[tid];
        const float2 r  = s.tab[toff[lvl] + p];
        float s0 = r.x, s1 = r.y;
#pragma unroll
        for (int j = 0; j < 8; j++) {
            const int    n  = st->nidx[j][tid];
            const float2 ll = st->nll[j][tid];
            const float dphi = ll.y - pl.y;
            const float dth  = ll.x - pl.x;
            float w = rsqrtf(fmaf(dphi, dphi, dth * dth));
            w = (n >= 0) ? w : 0.0f;
            const float2 v = s.tab[toff[lvl] + (n >= 0 ? n : 0)];
            s0 = fmaf(w, v.x, s0);
            s1 = fmaf(w, v.y, s1);
        }
        acc0[lvl] = s0; acc1[lvl] = s1;

        if (lvl == 3) {
            const int b = b0 + tid;
            float4* op = reinterpret_cast<float4*>(out + (size_t)b * 8);
            op[0] = make_float4(acc0[0], acc0[1], acc0[2], acc0[3]);
            op[1] = make_float4(acc1[0], acc1[1], acc1[2], acc1[3]);
        }

        if (i + 2 < nitems) {
            __syncthreads();    // everyone done reading stage st_i
            if (tid == 0) {
                const int ni   = i + 2;
                const int nlvl = ni & 3;
                const int ntile = blockIdx.x + (ni >> 2) * gridDim.x;
                issue_item(st, nlvl, ntile * TILE, smem_u32(&s.bar[st_i]),
                           neigh_ll, neigh_idx, pixel_ll, pixel_idx, B);
            }
        }
    }

    // tail: remaining B % TILE samples (and the unaligned-B fallback), last block
    const int tail_start = aligned ? ntiles * TILE : 0;
    if (blockIdx.x == gridDim.x - 1 && tail_start < B) {
        for (int b = tail_start + tid; b < B; b += TILE) {
            float t0[NLEV], t1[NLEV];
#pragma unroll
            for (int l = 0; l < NLEV; l++) {
                int    nidx[8];
                float2 nll[8];
#pragma unroll
                for (int j = 0; j < 8; j++)
                    nidx[j] = __ldcs(neigh_idx + (size_t)(l * 8 + j) * B + b);
#pragma unroll
                for (int j = 0; j < 8; j++)
                    nll[j] = __ldcs(neigh_ll + (size_t)(l * 8 + j) * B + b);
                const int    p  = __ldcs(pixel_idx + (size_t)l * B + b);
                const float2 pl = __ldcs(pixel_ll + (size_t)l * B + b);
                const float2 r  = s.tab[toff[l] + p];
                float s0 = r.x, s1 = r.y;
#pragma unroll
                for (int j = 0; j < 8; j++) {
                    const float dphi = nll[j].y - pl.y;
                    const float dth  = nll[j].x - pl.x;
                    float w = rsqrtf(fmaf(dphi, dphi, dth * dth));
                    w = (nidx[j] >= 0) ? w : 0.0f;
                    const float2 v = s.tab[toff[l] + (nidx[j] >= 0 ? nidx[j] : 0)];
                    s0 = fmaf(w, v.x, s0);
                    s1 = fmaf(w, v.y, s1);
                }
                t0[l] = s0; t1[l] = s1;
            }
            float4* op = reinterpret_cast<float4*>(out + (size_t)b * 8);
            op[0] = make_float4(t0[0], t0[1], t0[2], t0[3]);
            op[1] = make_float4(t1[0], t1[1], t1[2], t1[3]);
        }
    }
}

extern "C" void kernel_launch(void* const* d_in, const int* in_sizes, int n_in,
                              void* d_out, int out_size)
{
    // metadata order: params, pixel_latlon, neigh_latlon, pixel_index, neigh_index
    const float2* params2   = (const float2*)d_in[0];
    const float2* pixel_ll  = (const float2*)d_in[1];
    const float2* neigh_ll  = (const float2*)d_in[2];
    const int*    pixel_idx = (const int*)d_in[3];
    const int*    neigh_idx = (const int*)d_in[4];
    float*        out       = (float*)d_out;

    const int B = in_sizes[3] / NLEV;   // pixel_index has NLEV*B elements

    cudaFuncSetAttribute(heal_encoding_persist,
                         cudaFuncAttributeMaxDynamicSharedMemorySize, sizeof(Smem));

    heal_encoding_persist<<<NBLOCKS, TILE, sizeof(Smem)>>>(
        params2, pixel_ll, neigh_ll, pixel_idx, neigh_idx, out, B);
}